// round 8
// baseline (speedup 1.0000x reference)
#include <cuda_runtime.h>
#include <math.h>

#define Hh 64
#define Ff 10
#define Tt 60
#define Dd 6
#define Bb 2048

typedef unsigned long long ull;

// f32 recurrent weights as natural (gate0, gate1) pairs, per gate-warp:
// g_Uf[w][j*32+lane] = float4 { G0[j][lane], G1[j][lane], G0[j][lane+32], G1[j][lane+32] }
//   w=0: (G0,G1) = (U_i, U_ste);  w=1: (U_c, U_o)
__device__ __align__(16) float4 g_Uf[2][Hh * 32];

__global__ void prep_kernel(const float* __restrict__ Ui, const float* __restrict__ Us,
                            const float* __restrict__ Uc, const float* __restrict__ Uo) {
    int idx = blockIdx.x * blockDim.x + threadIdx.x;   // [0, 2*64*32)
    if (idx < 2 * Hh * 32) {
        int w = idx >> 11, r = idx & 2047;
        int j = r >> 5, lane = r & 31;
        const float* G0 = w ? Uc : Ui;
        const float* G1 = w ? Uo : Us;
        g_Uf[w][r] = make_float4(G0[j * Hh + lane],      G1[j * Hh + lane],
                                 G0[j * Hh + lane + 32], G1[j * Hh + lane + 32]);
    }
}

__device__ __forceinline__ float hsig(float v) {
    return __saturatef(fmaf(v, 0.16666667f, 0.5f));
}
__device__ __forceinline__ ull pack2(float lo, float hi) {
    ull r; asm("mov.b64 %0, {%1, %2};" : "=l"(r) : "f"(lo), "f"(hi)); return r;
}
__device__ __forceinline__ ull fma2(ull a, ull b, ull c) {
    ull d; asm("fma.rn.f32x2 %0, %1, %2, %3;" : "=l"(d) : "l"(a), "l"(b), "l"(c)); return d;
}
__device__ __forceinline__ ull add2(ull a, ull b) {
    ull d; asm("add.rn.f32x2 %0, %1, %2;" : "=l"(d) : "l"(a), "l"(b)); return d;
}
__device__ __forceinline__ float2 unpack2(ull v) {
    float lo, hi; asm("mov.b64 {%0, %1}, %2;" : "=f"(lo), "=f"(hi) : "l"(v));
    return make_float2(lo, hi);
}
// tanh(x) = 1 - 2/(exp(2x)+1): MUFU.EX2 + MUFU.RCP, abs err ~1e-6
__device__ __forceinline__ float ftanh(float x) {
    float e = __expf(2.0f * x);
    float r;
    asm("rcp.approx.f32 %0, %1;" : "=f"(r) : "f"(e + 1.0f));
    return fmaf(-2.0f, r, 1.0f);
}

// Block = 64 threads = 2 gate-split warps sharing 4 batches.
// Warp 0 computes gates (i,ste) for all 4 batches; warp 1 computes (c,o).
// Warp w runs the elementwise tail + fre for batches {2w, 2w+1}.
// Lane owns h-columns {lane, lane+32}.
__global__ __launch_bounds__(64) void sfm_kernel(
    const float* __restrict__ x,
    const float* __restrict__ W_i,   const float* __restrict__ b_i,
    const float* __restrict__ W_ste, const float* __restrict__ b_ste,
    const float* __restrict__ W_fre, const float* __restrict__ U_fre, const float* __restrict__ b_fre,
    const float* __restrict__ W_c,   const float* __restrict__ b_c,
    const float* __restrict__ W_o,   const float* __restrict__ b_o,
    const float* __restrict__ U_a,   const float* __restrict__ b_a,
    const float* __restrict__ W_p,   const float* __restrict__ b_p,
    float* __restrict__ out)
{
    __shared__ __align__(16) float4 sh_x4[Tt][Dd];   // (b0,b1,b2,b3)
    __shared__ __align__(16) ull sh_hd[Hh][4];       // dup pair (h,h) per [column j][batch]
    __shared__ __align__(16) ull sh_ex[2][32][4];    // [writer_warp][lane][hs*2+bl]
    __shared__ __align__(8)  float2 sh_cssn[Tt * Ff];
    __shared__ float sh_UfT[Ff * 65];                // transposed, padded: [f][j]

    const int tid  = threadIdx.x;
    const int lane = tid & 31;
    const int w    = tid >> 5;            // 0 = (i,ste) warp, 1 = (c,o) warp
    const int bbase = blockIdx.x * 4;

    // ---- one-time staging ----
    const float* xg = x + (size_t)bbase * (Tt * Dd);
    for (int i = tid; i < Tt * Dd; i += 64) {
        sh_x4[i / Dd][i % Dd] = make_float4(xg[0 * Tt * Dd + i], xg[1 * Tt * Dd + i],
                                            xg[2 * Tt * Dd + i], xg[3 * Tt * Dd + i]);
    }
    for (int i = tid; i < Ff * Hh; i += 64) {
        int f = i / Hh, j = i % Hh;
        sh_UfT[f * 65 + j] = U_fre[j * Ff + f];
    }
    for (int i = tid; i < Tt * Ff; i += 64) {
        int tt = i / Ff + 1, f = i % Ff;
        int m  = (tt * f) % Ff;
        float ang = (float)m * 0.62831853071795864769f; // 2*pi/10
        float s, c; sincosf(ang, &s, &c);
        sh_cssn[i] = make_float2(c, s);
    }
#pragma unroll
    for (int b = 0; b < 4; b++) sh_hd[tid][b] = 0ull;

    // ---- per-lane constants ----
    const int h0 = lane, h1 = lane + 32;
    const float* Wg0 = w ? W_c : W_i;
    const float* Wg1 = w ? W_o : W_ste;
    const float* bg0 = w ? b_c : b_i;
    const float* bg1 = w ? b_o : b_ste;
    // W as natural (g0,g1) pairs: [hslot][d]
    ull Wp_[2][Dd];
#pragma unroll
    for (int d = 0; d < Dd; d++) {
        Wp_[0][d] = pack2(Wg0[d * Hh + h0], Wg1[d * Hh + h0]);
        Wp_[1][d] = pack2(Wg0[d * Hh + h1], Wg1[d * Hh + h1]);
    }
    const ull bp_[2] = { pack2(bg0[h0], bg1[h0]), pack2(bg0[h1], bg1[h1]) };
    const float ba_[2] = { b_a[h0], b_a[h1] };
    float ua[Ff];
#pragma unroll
    for (int f = 0; f < Ff; f++) ua[f] = U_a[f];

    // fre duty: lanes 0..19 -> local batch fb = lane/10, freq ff = lane%10.
    const bool duty = (lane < 2 * Ff);
    const int  fb = lane / Ff, ff = lane % Ff;
    float wfre[Dd];
#pragma unroll
    for (int d = 0; d < Dd; d++) wfre[d] = W_fre[d * Ff + ff];
    const float bfre = b_fre[ff];

    // Oscillator state for my 2 tail batches: [bl][hslot][f]
    float sre[2][2][Ff], sim[2][2][Ff];
#pragma unroll
    for (int bl = 0; bl < 2; bl++)
#pragma unroll
        for (int hs = 0; hs < 2; hs++)
#pragma unroll
            for (int f = 0; f < Ff; f++) { sre[bl][hs][f] = 0.0f; sim[bl][hs][f] = 0.0f; }

    float hlast[2][2];   // [bl][hslot], for the epilogue

    __syncthreads();

    const ulonglong2* Ug = reinterpret_cast<const ulonglong2*>(&g_Uf[w][0]);

    for (int t = 0; t < Tt; t++) {
        // ---- seeds: acc[hs][b] = (g0,g1) bias + x_t @ (Wg0,Wg1) ----
        ull acc[2][4];
#pragma unroll
        for (int b = 0; b < 4; b++) { acc[0][b] = bp_[0]; acc[1][b] = bp_[1]; }
        float af = bfre;
#pragma unroll
        for (int d = 0; d < Dd; d++) {
            float4 xv = sh_x4[t][d];             // LDS.128 broadcast
            ull x0 = pack2(xv.x, xv.x);
            ull x1 = pack2(xv.y, xv.y);
            ull x2 = pack2(xv.z, xv.z);
            ull x3 = pack2(xv.w, xv.w);
            acc[0][0] = fma2(x0, Wp_[0][d], acc[0][0]);
            acc[1][0] = fma2(x0, Wp_[1][d], acc[1][0]);
            acc[0][1] = fma2(x1, Wp_[0][d], acc[0][1]);
            acc[1][1] = fma2(x1, Wp_[1][d], acc[1][1]);
            acc[0][2] = fma2(x2, Wp_[0][d], acc[0][2]);
            acc[1][2] = fma2(x2, Wp_[1][d], acc[1][2]);
            acc[0][3] = fma2(x3, Wp_[0][d], acc[0][3]);
            acc[1][3] = fma2(x3, Wp_[1][d], acc[1][3]);
            // fre x seed for my duty batch (global 2w+fb)
            float xd = fb ? (w ? xv.w : xv.y) : (w ? xv.z : xv.x);
            af = fmaf(xd, wfre[d], af);
        }

        // ---- recurrent matmul: f32 (g0,g1) U pairs x dup-h; no conversions ----
#pragma unroll 8
        for (int j = 0; j < Hh; j++) {
            ulonglong2 u  = Ug[j * 32 + lane];                  // LDG.128: (g0,g1)@h0, @h1
            ulonglong2 hA = *(const ulonglong2*)&sh_hd[j][0];   // dup pairs b0,b1 (bcast)
            ulonglong2 hB = *(const ulonglong2*)&sh_hd[j][2];   // dup pairs b2,b3
            acc[0][0] = fma2(hA.x, u.x, acc[0][0]);
            acc[1][0] = fma2(hA.x, u.y, acc[1][0]);
            acc[0][1] = fma2(hA.y, u.x, acc[0][1]);
            acc[1][1] = fma2(hA.y, u.y, acc[1][1]);
            acc[0][2] = fma2(hB.x, u.x, acc[0][2]);
            acc[1][2] = fma2(hB.x, u.y, acc[1][2]);
            acc[0][3] = fma2(hB.y, u.x, acc[0][3]);
            acc[1][3] = fma2(hB.y, u.y, acc[1][3]);
            if (duty) {
                ull hown = w ? (fb ? hB.y : hB.x) : (fb ? hA.y : hA.x);
                af = fmaf(unpack2(hown).x, sh_UfT[ff * 65 + j], af);
            }
        }
        const float frev = hsig(af);   // valid on duty lanes

        // ---- exchange: send my gate pairs for the PEER's 2 batches ----
        {
            int pb = 2 * (1 - w);
            ulonglong2* dst = reinterpret_cast<ulonglong2*>(&sh_ex[w][lane][0]);
            dst[0] = make_ulonglong2(acc[0][pb],     acc[1][pb]);       // bl=0: hs0, hs1
            dst[1] = make_ulonglong2(acc[0][pb + 1], acc[1][pb + 1]);   // bl=1
        }
        __syncthreads();   // exchange visible; sh_hd reads of this step done
        ull peer[2][2];    // [bl][hs]
        {
            const ulonglong2* src = reinterpret_cast<const ulonglong2*>(&sh_ex[1 - w][lane][0]);
            ulonglong2 s0 = src[0], s1 = src[1];
            peer[0][0] = s0.x; peer[0][1] = s0.y;
            peer[1][0] = s1.x; peer[1][1] = s1.y;
        }

        // ---- elementwise tail for my 2 batches ----
        float cs[Ff], sn[Ff];
#pragma unroll
        for (int f = 0; f < Ff; f++) {
            float2 cn = sh_cssn[t * Ff + f];
            cs[f] = cn.x; sn[f] = cn.y;
        }
#pragma unroll
        for (int bl = 0; bl < 2; bl++) {
            float fre_b[Ff];
#pragma unroll
            for (int f = 0; f < Ff; f++)
                fre_b[f] = __shfl_sync(0xffffffffu, frev, bl * Ff + f);
            int b = 2 * w + bl;   // my global-local batch index within block
#pragma unroll
            for (int hs = 0; hs < 2; hs++) {
                float2 mine = unpack2(acc[hs][b]);    // my gates: w=0 -> (i,ste); w=1 -> (c,o)
                float2 thrs = unpack2(peer[bl][hs]);  // peer gates
                float pi   = w ? thrs.x : mine.x;
                float pste = w ? thrs.y : mine.y;
                float pc   = w ? mine.x : thrs.x;
                float po   = w ? mine.y : thrs.y;
                float iv = hsig(pi);
                float sv = hsig(pste);
                float ov = hsig(po);
                float cv = iv * ftanh(pc);
                float acca = ba_[hs];
#pragma unroll
                for (int f = 0; f < Ff; f++) {
                    float fv = sv * fre_b[f];
                    float r = fmaf(fv, sre[bl][hs][f], cv * cs[f]);
                    float m = fmaf(fv, sim[bl][hs][f], cv * sn[f]);
                    sre[bl][hs][f] = r;
                    sim[bl][hs][f] = m;
                    acca = fmaf(fmaf(r, r, m * m), ua[f], acca);
                }
                float hv = ov * ftanh(acca);
                hlast[bl][hs] = hv;
            }
        }
        // Publish my 2 batches' h as dup pairs: columns h0 and h1, batches 2w,2w+1.
        {
            ulonglong2* r0 = reinterpret_cast<ulonglong2*>(&sh_hd[h0][2 * w]);
            ulonglong2* r1 = reinterpret_cast<ulonglong2*>(&sh_hd[h1][2 * w]);
            *r0 = make_ulonglong2(pack2(hlast[0][0], hlast[0][0]),
                                  pack2(hlast[1][0], hlast[1][0]));
            *r1 = make_ulonglong2(pack2(hlast[0][1], hlast[0][1]),
                                  pack2(hlast[1][1], hlast[1][1]));
        }
        __syncthreads();   // new h visible for next step
    }

    // ---- projection: out[b] = h @ W_p + b_p (warp butterfly over my 2 batches) ----
    {
        float wp0 = W_p[h0], wp1 = W_p[h1];
        float p0 = fmaf(hlast[0][0], wp0, hlast[0][1] * wp1);
        float p1 = fmaf(hlast[1][0], wp0, hlast[1][1] * wp1);
        ull pp = pack2(p0, p1);
#pragma unroll
        for (int off = 16; off >= 1; off >>= 1)
            pp = add2(pp, __shfl_xor_sync(0xffffffffu, pp, off));
        if (lane == 0) {
            float2 r = unpack2(pp);
            float bpv = b_p[0];
            out[bbase + 2 * w]     = r.x + bpv;
            out[bbase + 2 * w + 1] = r.y + bpv;
        }
    }
}

extern "C" void kernel_launch(void* const* d_in, const int* in_sizes, int n_in,
                              void* d_out, int out_size) {
    const float* x     = (const float*)d_in[0];
    const float* W_i   = (const float*)d_in[1];
    const float* U_i   = (const float*)d_in[2];
    const float* b_i   = (const float*)d_in[3];
    const float* W_ste = (const float*)d_in[4];
    const float* U_ste = (const float*)d_in[5];
    const float* b_ste = (const float*)d_in[6];
    const float* W_fre = (const float*)d_in[7];
    const float* U_fre = (const float*)d_in[8];
    const float* b_fre = (const float*)d_in[9];
    const float* W_c   = (const float*)d_in[10];
    const float* U_c   = (const float*)d_in[11];
    const float* b_c   = (const float*)d_in[12];
    const float* W_o   = (const float*)d_in[13];
    const float* U_o   = (const float*)d_in[14];
    const float* b_o   = (const float*)d_in[15];
    const float* U_a   = (const float*)d_in[16];
    const float* b_a   = (const float*)d_in[17];
    const float* W_p   = (const float*)d_in[18];
    const float* b_p   = (const float*)d_in[19];

    (void)in_sizes; (void)n_in; (void)out_size;

    prep_kernel<<<(2 * Hh * 32 + 255) / 256, 256>>>(U_i, U_ste, U_c, U_o);
    sfm_kernel<<<Bb / 4, 64>>>(x, W_i, b_i, W_ste, b_ste, W_fre, U_fre, b_fre,
                               W_c, b_c, W_o, b_o, U_a, b_a, W_p, b_p,
                               (float*)d_out);
}